// round 2
// baseline (speedup 1.0000x reference)
#include <cuda_runtime.h>

#define VSZ   50257
#define Dk    50
#define TT    1024
#define BSZ   1024
#define NU1   32
#define NU2   64
#define NGLU  128
#define BB    8
#define NT    384

// Precomputed emb @ kx1 + b1[0] table: [V, 96] fp32 (L2-resident, 19.3MB)
__device__ float g_proj1[VSZ * 96];

typedef unsigned long long u64;

__device__ __forceinline__ u64 pk2(float a, float b) {
    u64 r; asm("mov.b64 %0, {%1, %2};" : "=l"(r) : "f"(a), "f"(b)); return r;
}
__device__ __forceinline__ void upk2(u64 v, float& a, float& b) {
    asm("mov.b64 {%0, %1}, %2;" : "=f"(a), "=f"(b) : "l"(v));
}
__device__ __forceinline__ u64 ffma2(u64 a, u64 b, u64 c) {
    u64 d; asm("fma.rn.f32x2 %0, %1, %2, %3;" : "=l"(d) : "l"(a), "l"(b), "l"(c)); return d;
}
__device__ __forceinline__ u64 fadd2(u64 a, u64 b) {
    u64 d; asm("add.rn.f32x2 %0, %1, %2;" : "=l"(d) : "l"(a), "l"(b)); return d;
}
__device__ __forceinline__ float sgm(float x) { return 1.0f / (1.0f + __expf(-x)); }
__device__ __forceinline__ float tnh(float x) { return 2.0f * sgm(2.0f * x) - 1.0f; }

// GRU gate update for a batch pair packed in u64 lanes.
__device__ __forceinline__ u64 gru_gate(u64 xz, u64 hz, u64 xr, u64 hr,
                                        u64 xh, u64 hh, u64 hold) {
    float az0, az1, ar0, ar1, xh0, xh1, hh0, hh1, g0, g1;
    upk2(fadd2(xz, hz), az0, az1);
    upk2(fadd2(xr, hr), ar0, ar1);
    upk2(xh, xh0, xh1); upk2(hh, hh0, hh1); upk2(hold, g0, g1);
    float z0 = sgm(az0), z1 = sgm(az1);
    float r0 = sgm(ar0), r1 = sgm(ar1);
    float c0 = tnh(xh0 + r0 * hh0);
    float c1 = tnh(xh1 + r1 * hh1);
    return pk2(z0 * g0 + (1.0f - z0) * c0, z1 * g1 + (1.0f - z1) * c1);
}

// ---------------------------------------------------------------------------
// g_proj1[v][j] = sum_d emb[v][d]*kx1[d][j] + b1[0][j]
// ---------------------------------------------------------------------------
__global__ void proj_kernel(const float* __restrict__ emb,
                            const float* __restrict__ kx1,
                            const float* __restrict__ b1) {
    __shared__ float kxs[Dk * 96];
    __shared__ float embs[16 * Dk];
    int tid = threadIdx.x;
    for (int i = tid; i < Dk * 96; i += 256) kxs[i] = kx1[i];
    int vbase = blockIdx.x * 16;
    for (int i = tid; i < 16 * Dk; i += 256) {
        int r = i / Dk, d = i - r * Dk;
        int v = vbase + r;
        embs[i] = (v < VSZ) ? emb[v * Dk + d] : 0.0f;
    }
    __syncthreads();
    for (int i = tid; i < 16 * 96; i += 256) {
        int r = i / 96, j = i - r * 96;
        int v = vbase + r;
        if (v >= VSZ) continue;
        float acc = b1[j];
        #pragma unroll
        for (int d = 0; d < Dk; d++)
            acc = fmaf(embs[r * Dk + d], kxs[d * 96 + j], acc);
        g_proj1[v * 96 + j] = acc;
    }
}

// ---------------------------------------------------------------------------
// Shared memory layout (dynamic, ~206KB)
// ---------------------------------------------------------------------------
#define OFF_W1D   0         // [32][96]  u64  24576
#define OFF_WX2D  24576     // [32][192] u64  49152
#define OFF_WH2F  73728     // [64][192] f32  49152
#define OFF_P1    122880    // [384][8]  u64  24576
#define OFF_P2    147456    // [384][8]  u64  24576
#define OFF_P3    172032    // [384][8]  u64  24576
#define OFF_BH1D  196608    // [96]  u64 768
#define OFF_BX2D  197376    // [192] u64 1536
#define OFF_BH2D  198912    // [192] u64 1536
#define OFF_H1P   200448    // [32][4] u64 1024
#define OFF_H2P   201472    // [64][4] u64 2048
#define OFF_XG1   203520    // [2][96][8] f32 6144
#define OFF_TOK   209664    // [8][32] int 1024
#define SMEM_SZ   210688

__device__ __forceinline__ u64 sumP(const u64* p, int cp, int k, int nseg, int stride) {
    u64 a = fadd2(p[(0 * stride + cp) * 8 + k], p[(1 * stride + cp) * 8 + k]);
    u64 b = fadd2(p[(2 * stride + cp) * 8 + k], p[(3 * stride + cp) * 8 + k]);
    u64 s = fadd2(a, b);
    if (nseg == 8) {
        u64 c = fadd2(p[(4 * stride + cp) * 8 + k], p[(5 * stride + cp) * 8 + k]);
        u64 d = fadd2(p[(6 * stride + cp) * 8 + k], p[(7 * stride + cp) * 8 + k]);
        s = fadd2(s, fadd2(c, d));
    }
    return s;
}

__global__ void __launch_bounds__(NT, 1) rnn_kernel(
    const int*   __restrict__ tokens,
    const float* __restrict__ kh1,   // [32][96]
    const float* __restrict__ b1,    // [2][96]
    const float* __restrict__ kx2,   // [32][192]
    const float* __restrict__ kh2,   // [64][192]
    const float* __restrict__ b2,    // [2][192]
    const float* __restrict__ wg,    // [64][256]
    const float* __restrict__ bg,    // [256]
    const float* __restrict__ wd,    // [128]
    const float* __restrict__ bd,    // [1]
    float*       __restrict__ out)
{
    extern __shared__ char smem[];
    u64*   w1d   = (u64*)  (smem + OFF_W1D);
    u64*   wx2d  = (u64*)  (smem + OFF_WX2D);
    float* wh2f  = (float*)(smem + OFF_WH2F);
    u64*   p1    = (u64*)  (smem + OFF_P1);
    u64*   p2    = (u64*)  (smem + OFF_P2);
    u64*   p3    = (u64*)  (smem + OFF_P3);
    u64*   bh1d  = (u64*)  (smem + OFF_BH1D);
    u64*   bx2d  = (u64*)  (smem + OFF_BX2D);
    u64*   bh2d  = (u64*)  (smem + OFF_BH2D);
    u64*   h1p   = (u64*)  (smem + OFF_H1P);   // [u][bp]
    u64*   h2p   = (u64*)  (smem + OFF_H2P);
    float* xg1f  = (float*)(smem + OFF_XG1);   // [buf][j][b]
    int*   tokbuf= (int*)  (smem + OFF_TOK);   // [b][slot]

    const int tid = threadIdx.x;
    const int b0  = blockIdx.x * BB;

    // ---------------- prologue: stage weights, init state ----------------
    for (int i = tid; i < NU1 * 96; i += NT)  { float w = kh1[i]; w1d[i]  = pk2(w, w); }
    for (int i = tid; i < NU1 * 192; i += NT) { float w = kx2[i]; wx2d[i] = pk2(w, w); }
    for (int i = tid; i < NU2 * 192; i += NT) wh2f[i] = kh2[i];
    if (tid < 96)  { float b = b1[96 + tid]; bh1d[tid] = pk2(b, b); }
    if (tid < 192) {
        float bx = b2[tid];        bx2d[tid] = pk2(bx, bx);
        float bh = b2[192 + tid];  bh2d[tid] = pk2(bh, bh);
    }
    if (tid < NU1 * 4) h1p[tid] = 0ull;
    if (tid < NU2 * 4) h2p[tid] = 0ull;
    if (tid < 256) {
        int b = tid >> 5, o = tid & 31;
        tokbuf[b * 32 + o] = tokens[(b0 + b) * TT + o];
    }
    __syncthreads();
    // gather xg1[0] -> buf0, xg1[1] -> buf1
    #pragma unroll
    for (int g = 0; g < 2; g++) {
        int idx = tid + NT * g;     // 0..767
        int b = idx / 96, j = idx - 96 * (idx / 96);
        xg1f[(0 * 96 + j) * 8 + b] = __ldg(&g_proj1[tokbuf[b * 32 + 0] * 96 + j]);
        xg1f[(1 * 96 + j) * 8 + b] = __ldg(&g_proj1[tokbuf[b * 32 + 1] * 96 + j]);
    }
    __syncthreads();
    // GRU1 step 0 (h=0 -> hm1 = bh1)
    if (tid < 128) {
        int i = tid & 31, bp = tid >> 5;
        u64 xz = *(const u64*)&xg1f[(0 * 96 + i)      * 8 + 2 * bp];
        u64 xr = *(const u64*)&xg1f[(0 * 96 + 32 + i) * 8 + 2 * bp];
        u64 xh = *(const u64*)&xg1f[(0 * 96 + 64 + i) * 8 + 2 * bp];
        h1p[i * 4 + bp] = gru_gate(xz, bh1d[i], xr, bh1d[32 + i], xh, bh1d[64 + i], 0ull);
    }
    __syncthreads();

    // precomputed unit indices
    const int cp96 = tid % 96, us96 = tid / 96;       // G2/G3
    const int cp48 = tid % 48, us48 = tid / 48;       // G1
    const int gb0 = tid / 96,           gj0 = tid - 96 * (tid / 96);
    const int gb1 = (tid + NT) / 96,    gj1 = (tid + NT) - 96 * ((tid + NT) / 96);

    float gv0 = 0.0f, gv1 = 0.0f;

    #pragma unroll 1
    for (int k = 0; k < TT; k++) {
        // ========== Phase A: gathers + 3 GEMMs ==========
        if (k < TT - 2) {
            int slot = (k + 2) & 31;
            gv0 = __ldg(&g_proj1[tokbuf[gb0 * 32 + slot] * 96 + gj0]);
            gv1 = __ldg(&g_proj1[tokbuf[gb1 * 32 + slot] * 96 + gj1]);
        }
        // --- G1: hm1(next) partial: cols {2cp48, 2cp48+1}, 4u segment ---
        {
            u64 acc[2][4];
            u64 bA = (us48 == 0) ? bh1d[2 * cp48]     : 0ull;
            u64 bBv= (us48 == 0) ? bh1d[2 * cp48 + 1] : 0ull;
            #pragma unroll
            for (int p = 0; p < 4; p++) { acc[0][p] = bA; acc[1][p] = bBv; }
            int u0 = us48 * 4;
            #pragma unroll
            for (int uu = 0; uu < 4; uu++) {
                int u = u0 + uu;
                ulonglong2 w  = *(const ulonglong2*)&w1d[u * 96 + 2 * cp48];
                ulonglong2 hA = *(const ulonglong2*)&h1p[u * 4];
                ulonglong2 hB = *(const ulonglong2*)&h1p[u * 4 + 2];
                acc[0][0] = ffma2(w.x, hA.x, acc[0][0]); acc[0][1] = ffma2(w.x, hA.y, acc[0][1]);
                acc[0][2] = ffma2(w.x, hB.x, acc[0][2]); acc[0][3] = ffma2(w.x, hB.y, acc[0][3]);
                acc[1][0] = ffma2(w.y, hA.x, acc[1][0]); acc[1][1] = ffma2(w.y, hA.y, acc[1][1]);
                acc[1][2] = ffma2(w.y, hB.x, acc[1][2]); acc[1][3] = ffma2(w.y, hB.y, acc[1][3]);
            }
            ulonglong2* pp = (ulonglong2*)(p1 + tid * 8);
            pp[0] = make_ulonglong2(acc[0][0], acc[0][1]);
            pp[1] = make_ulonglong2(acc[0][2], acc[0][3]);
            pp[2] = make_ulonglong2(acc[1][0], acc[1][1]);
            pp[3] = make_ulonglong2(acc[1][2], acc[1][3]);
        }
        // --- G2: xg2 partial: cols {2cp96, 2cp96+1}, 8u segment ---
        {
            u64 acc[2][4];
            u64 bA = (us96 == 0) ? bx2d[2 * cp96]     : 0ull;
            u64 bBv= (us96 == 0) ? bx2d[2 * cp96 + 1] : 0ull;
            #pragma unroll
            for (int p = 0; p < 4; p++) { acc[0][p] = bA; acc[1][p] = bBv; }
            int u0 = us96 * 8;
            #pragma unroll
            for (int uu = 0; uu < 8; uu++) {
                int u = u0 + uu;
                ulonglong2 w  = *(const ulonglong2*)&wx2d[u * 192 + 2 * cp96];
                ulonglong2 hA = *(const ulonglong2*)&h1p[u * 4];
                ulonglong2 hB = *(const ulonglong2*)&h1p[u * 4 + 2];
                acc[0][0] = ffma2(w.x, hA.x, acc[0][0]); acc[0][1] = ffma2(w.x, hA.y, acc[0][1]);
                acc[0][2] = ffma2(w.x, hB.x, acc[0][2]); acc[0][3] = ffma2(w.x, hB.y, acc[0][3]);
                acc[1][0] = ffma2(w.y, hA.x, acc[1][0]); acc[1][1] = ffma2(w.y, hA.y, acc[1][1]);
                acc[1][2] = ffma2(w.y, hB.x, acc[1][2]); acc[1][3] = ffma2(w.y, hB.y, acc[1][3]);
            }
            ulonglong2* pp = (ulonglong2*)(p2 + tid * 8);
            pp[0] = make_ulonglong2(acc[0][0], acc[0][1]);
            pp[1] = make_ulonglong2(acc[0][2], acc[0][3]);
            pp[2] = make_ulonglong2(acc[1][0], acc[1][1]);
            pp[3] = make_ulonglong2(acc[1][2], acc[1][3]);
        }
        // --- G3: hm2 partial: cols {2cp96, 2cp96+1}, 16u segment ---
        {
            u64 acc[2][4];
            u64 bA = (us96 == 0) ? bh2d[2 * cp96]     : 0ull;
            u64 bBv= (us96 == 0) ? bh2d[2 * cp96 + 1] : 0ull;
            #pragma unroll
            for (int p = 0; p < 4; p++) { acc[0][p] = bA; acc[1][p] = bBv; }
            int u0 = us96 * 16;
            #pragma unroll
            for (int uu = 0; uu < 16; uu++) {
                int u = u0 + uu;
                float2 wf = *(const float2*)&wh2f[u * 192 + 2 * cp96];
                u64 w0 = pk2(wf.x, wf.x), w1 = pk2(wf.y, wf.y);
                ulonglong2 hA = *(const ulonglong2*)&h2p[u * 4];
                ulonglong2 hB = *(const ulonglong2*)&h2p[u * 4 + 2];
                acc[0][0] = ffma2(w0, hA.x, acc[0][0]); acc[0][1] = ffma2(w0, hA.y, acc[0][1]);
                acc[0][2] = ffma2(w0, hB.x, acc[0][2]); acc[0][3] = ffma2(w0, hB.y, acc[0][3]);
                acc[1][0] = ffma2(w1, hA.x, acc[1][0]); acc[1][1] = ffma2(w1, hA.y, acc[1][1]);
                acc[1][2] = ffma2(w1, hB.x, acc[1][2]); acc[1][3] = ffma2(w1, hB.y, acc[1][3]);
            }
            ulonglong2* pp = (ulonglong2*)(p3 + tid * 8);
            pp[0] = make_ulonglong2(acc[0][0], acc[0][1]);
            pp[1] = make_ulonglong2(acc[0][2], acc[0][3]);
            pp[2] = make_ulonglong2(acc[1][0], acc[1][1]);
            pp[3] = make_ulonglong2(acc[1][2], acc[1][3]);
        }
        __syncthreads();

        // ========== Phase B: gates + gather stores + token reload ==========
        if (k < TT - 2) {
            int buf = (k + 2) & 1;
            xg1f[(buf * 96 + gj0) * 8 + gb0] = gv0;
            xg1f[(buf * 96 + gj1) * 8 + gb1] = gv1;
        }
        if (tid < 256) {
            // GRU2 gates, step k: h2 <- f(xg2, hm2, h2)
            int i = tid & 63, bp = tid >> 6;
            int cpz = i >> 1, par = (i & 1) * 4 + bp;
            u64 xz = sumP(p2, cpz,      par, 4, 96);
            u64 xr = sumP(p2, 32 + cpz, par, 4, 96);
            u64 xh = sumP(p2, 64 + cpz, par, 4, 96);
            u64 hz = sumP(p3, cpz,      par, 4, 96);
            u64 hr = sumP(p3, 32 + cpz, par, 4, 96);
            u64 hh = sumP(p3, 64 + cpz, par, 4, 96);
            u64 hold = h2p[i * 4 + bp];
            h2p[i * 4 + bp] = gru_gate(xz, hz, xr, hr, xh, hh, hold);
            // token chunk reload
            if (((k + 3) & 31) == 0 && (k + 3) < TT) {
                int b = tid >> 5, o = tid & 31;
                tokbuf[b * 32 + o] = tokens[(b0 + b) * TT + (k + 3) + o];
            }
        } else if (k < TT - 1) {
            // GRU1 gates, step k+1
            int t2 = tid - 256;
            int i = t2 & 31, bp = t2 >> 5;
            int cpz = i >> 1, par = (i & 1) * 4 + bp;
            u64 hz = sumP(p1, cpz,      par, 8, 48);
            u64 hr = sumP(p1, 16 + cpz, par, 8, 48);
            u64 hh = sumP(p1, 32 + cpz, par, 8, 48);
            const float* xb = xg1f + ((k + 1) & 1) * 96 * 8;
            u64 xz = *(const u64*)&xb[(i)      * 8 + 2 * bp];
            u64 xr = *(const u64*)&xb[(32 + i) * 8 + 2 * bp];
            u64 xh = *(const u64*)&xb[(64 + i) * 8 + 2 * bp];
            u64 hold = h1p[i * 4 + bp];
            h1p[i * 4 + bp] = gru_gate(xz, hz, xr, hr, xh, hh, hold);
        }
        __syncthreads();
    }

    // ================= Epilogue: GLU + dense + sigmoid =================
    float* ags = (float*)(smem + OFF_P1);   // [8][256]
    float* gws = (float*)(smem + OFF_P2);   // [8][128]
    if (tid < 256) {
        int c = tid;
        u64 acc[4];
        u64 bgp = pk2(bg[c], bg[c]);
        #pragma unroll
        for (int p = 0; p < 4; p++) acc[p] = bgp;
        #pragma unroll
        for (int u = 0; u < NU2; u++) {
            ulonglong2 hA = *(const ulonglong2*)&h2p[u * 4];
            ulonglong2 hB = *(const ulonglong2*)&h2p[u * 4 + 2];
            float wv = __ldg(&wg[u * 256 + c]);
            u64 w = pk2(wv, wv);
            acc[0] = ffma2(w, hA.x, acc[0]); acc[1] = ffma2(w, hA.y, acc[1]);
            acc[2] = ffma2(w, hB.x, acc[2]); acc[3] = ffma2(w, hB.y, acc[3]);
        }
        #pragma unroll
        for (int p = 0; p < 4; p++) {
            float f0, f1; upk2(acc[p], f0, f1);
            ags[(2 * p) * 256 + c] = f0;
            ags[(2 * p + 1) * 256 + c] = f1;
        }
    }
    __syncthreads();
    for (int i = tid; i < BB * NGLU; i += NT) {
        int b = i >> 7, kk = i & 127;
        float g = ags[b * 256 + kk] * sgm(ags[b * 256 + NGLU + kk]);
        gws[b * NGLU + kk] = g * __ldg(&wd[kk]);
    }
    __syncthreads();
    if (tid < BB) {
        float s = bd[0];
        #pragma unroll
        for (int kk = 0; kk < NGLU; kk++) s += gws[tid * NGLU + kk];
        out[b0 + tid] = sgm(s);
    }
}

// ---------------------------------------------------------------------------
extern "C" void kernel_launch(void* const* d_in, const int* in_sizes, int n_in,
                              void* d_out, int out_size) {
    (void)in_sizes; (void)n_in; (void)out_size;
    const int*   tokens = (const int*)  d_in[0];
    const float* emb    = (const float*)d_in[1];
    const float* kx1    = (const float*)d_in[2];
    const float* kh1    = (const float*)d_in[3];
    const float* b1     = (const float*)d_in[4];
    const float* kx2    = (const float*)d_in[5];
    const float* kh2    = (const float*)d_in[6];
    const float* b2     = (const float*)d_in[7];
    const float* wg     = (const float*)d_in[8];
    const float* bg     = (const float*)d_in[9];
    const float* wd     = (const float*)d_in[10];
    const float* bd     = (const float*)d_in[11];

    static int smem_set = 0;
    if (!smem_set) {
        cudaFuncSetAttribute(rnn_kernel,
                             cudaFuncAttributeMaxDynamicSharedMemorySize, SMEM_SZ);
        smem_set = 1;
    }

    proj_kernel<<<(VSZ + 15) / 16, 256>>>(emb, kx1, b1);
    rnn_kernel<<<BSZ / BB, NT, SMEM_SZ>>>(tokens, kh1, b1, kx2, kh2, b2,
                                          wg, bg, wd, bd, (float*)d_out);
}

// round 3
// speedup vs baseline: 1.1873x; 1.1873x over previous
#include <cuda_runtime.h>

#define VSZ 50257
#define Dk  50
#define TT  1024
#define BSZ 1024
#define BB  8
#define NT  352

// Precomputed emb @ kx1 + b1[0] table: [V, 96] fp32 (L2-resident, 19.3MB)
__device__ float g_proj1[VSZ * 96];

typedef unsigned long long u64;

__device__ __forceinline__ u64 pk2(float a, float b) {
    u64 r; asm("mov.b64 %0, {%1, %2};" : "=l"(r) : "f"(a), "f"(b)); return r;
}
__device__ __forceinline__ void upk2(u64 v, float& a, float& b) {
    asm("mov.b64 {%0, %1}, %2;" : "=f"(a), "=f"(b) : "l"(v));
}
__device__ __forceinline__ u64 ffma2(u64 a, u64 b, u64 c) {
    u64 d; asm("fma.rn.f32x2 %0, %1, %2, %3;" : "=l"(d) : "l"(a), "l"(b), "l"(c)); return d;
}
__device__ __forceinline__ u64 fadd2(u64 a, u64 b) {
    u64 d; asm("add.rn.f32x2 %0, %1, %2;" : "=l"(d) : "l"(a), "l"(b)); return d;
}
__device__ __forceinline__ float sgm(float x) { return 1.0f / (1.0f + __expf(-x)); }
__device__ __forceinline__ float tnh(float x) { return 2.0f * sgm(2.0f * x) - 1.0f; }

// GRU gate update for two batch values packed in f32x2 lanes.
__device__ __forceinline__ u64 gru_gate(u64 xz, u64 hz, u64 xr, u64 hr,
                                        u64 xh, u64 hh, u64 hold) {
    float az0, az1, ar0, ar1, xh0, xh1, hh0, hh1, g0, g1;
    upk2(fadd2(xz, hz), az0, az1);
    upk2(fadd2(xr, hr), ar0, ar1);
    upk2(xh, xh0, xh1); upk2(hh, hh0, hh1); upk2(hold, g0, g1);
    float z0 = sgm(az0), z1 = sgm(az1);
    float r0 = sgm(ar0), r1 = sgm(ar1);
    float c0 = tnh(xh0 + r0 * hh0);
    float c1 = tnh(xh1 + r1 * hh1);
    return pk2(z0 * g0 + (1.0f - z0) * c0, z1 * g1 + (1.0f - z1) * c1);
}

// ---------------------------------------------------------------------------
// g_proj1[v][j] = sum_d emb[v][d]*kx1[d][j] + b1[0][j]
// ---------------------------------------------------------------------------
__global__ void proj_kernel(const float* __restrict__ emb,
                            const float* __restrict__ kx1,
                            const float* __restrict__ b1) {
    __shared__ float kxs[Dk * 96];
    __shared__ float embs[16 * Dk];
    int tid = threadIdx.x;
    for (int i = tid; i < Dk * 96; i += 256) kxs[i] = kx1[i];
    int vbase = blockIdx.x * 16;
    for (int i = tid; i < 16 * Dk; i += 256) {
        int r = i / Dk, d = i - r * Dk;
        int v = vbase + r;
        embs[i] = (v < VSZ) ? emb[v * Dk + d] : 0.0f;
    }
    __syncthreads();
    for (int i = tid; i < 16 * 96; i += 256) {
        int r = i / 96, j = i - r * 96;
        int v = vbase + r;
        if (v >= VSZ) continue;
        float acc = b1[j];
        #pragma unroll
        for (int d = 0; d < Dk; d++)
            acc = fmaf(embs[r * Dk + d], kxs[d * 96 + j], acc);
        g_proj1[v * 96 + j] = acc;
    }
}

// ---------------------------------------------------------------------------
// Shared layout (bytes). States h*d store each scalar DUPLICATED as (h,h) u64.
// Result buffers padded to 10 floats/col-row to avoid bank conflicts.
// ---------------------------------------------------------------------------
#define OFF_H1D  0        // [32][8] u64   2048   (h1, dup pairs)
#define OFF_H2D  2048     // [64][8] u64   4096
#define OFF_XG2  6144     // [192][10] f32 7680   (h1 @ kx2 + b)
#define OFF_HM2  13824    // [192][10] f32 7680   (h2 @ kh2 + b)
#define OFF_HM1  21504    // [96][10]  f32 3840   (h1 @ kh1 + b, for t+1)
#define OFF_XG1  25344    // [2][96][10] f32 7680 (gathered proj, dbl buf)
#define OFF_TOK  33024    // [8][32] int   1024
#define OFF_AGS  6144     // epilogue alias [8][256] f32
#define OFF_GWS  14336    // epilogue alias [8][128] f32
#define SMEM_BYTES 34048

__global__ void __launch_bounds__(NT, 1) rnn_kernel(
    const int*   __restrict__ tokens,
    const float* __restrict__ kh1,   // [32][96]
    const float* __restrict__ b1,    // [2][96]
    const float* __restrict__ kx2,   // [32][192]
    const float* __restrict__ kh2,   // [64][192]
    const float* __restrict__ b2,    // [2][192]
    const float* __restrict__ wg,    // [64][256]
    const float* __restrict__ bg,    // [256]
    const float* __restrict__ wd,    // [128]
    const float* __restrict__ bd,    // [1]
    float*       __restrict__ out)
{
    __shared__ __align__(16) char sbuf[SMEM_BYTES];
    u64*   h1d  = (u64*)(sbuf + OFF_H1D);
    u64*   h2d  = (u64*)(sbuf + OFF_H2D);
    float* xg2f = (float*)(sbuf + OFF_XG2);
    float* hm2f = (float*)(sbuf + OFF_HM2);
    float* hm1f = (float*)(sbuf + OFF_HM1);
    float* xg1f = (float*)(sbuf + OFF_XG1);
    int*   tok  = (int*)(sbuf + OFF_TOK);

    const int tid = threadIdx.x;
    const int b0  = blockIdx.x * BB;

    // role decode
    const int c3  = tid % 96;              // G3 col-pair  (tid < 192)
    const int hf3 = tid / 96;              // G3 batch half
    const int c2  = tid - 192;             // G2 col-pair  (192..288)
    const int c1  = tid - 288;             // G1 col-pair  (288..336)

    // ---- weights into registers (col-pair packed, NO duplication) ----
    u64 wq[64];
    u64 bq = 0ull;
    if (tid < 192) {
        #pragma unroll
        for (int u = 0; u < 64; u++) {
            float2 w = *(const float2*)&kh2[u * 192 + 2 * c3];
            wq[u] = pk2(w.x, w.y);
        }
        float2 bb = *(const float2*)&b2[192 + 2 * c3];
        bq = pk2(bb.x, bb.y);
    } else if (tid < 288) {
        #pragma unroll
        for (int u = 0; u < 32; u++) {
            float2 w = *(const float2*)&kx2[u * 192 + 2 * c2];
            wq[u] = pk2(w.x, w.y);
        }
        float2 bb = *(const float2*)&b2[2 * c2];
        bq = pk2(bb.x, bb.y);
    } else if (tid < 336) {
        #pragma unroll
        for (int u = 0; u < 32; u++) {
            float2 w = *(const float2*)&kh1[u * 96 + 2 * c1];
            wq[u] = pk2(w.x, w.y);
        }
        float2 bb = *(const float2*)&b1[96 + 2 * c1];
        bq = pk2(bb.x, bb.y);
    }

    // ---- init: zero states, token chunk 0 ----
    for (int i = tid; i < (2048 + 4096) / 8; i += NT) ((u64*)sbuf)[i] = 0ull;
    if (tid < 256) {
        int b = tid >> 5, o = tid & 31;
        tok[b * 32 + o] = tokens[(b0 + b) * TT + o];
    }
    __syncthreads();
    // prefill gather buffers for t=0,1
    for (int i = tid; i < 768; i += NT) {
        int b = i / 96, j = i - 96 * (i / 96);
        xg1f[0 * 960 + j * 10 + b] = __ldg(&g_proj1[tok[b * 32 + 0] * 96 + j]);
        xg1f[1 * 960 + j * 10 + b] = __ldg(&g_proj1[tok[b * 32 + 1] * 96 + j]);
    }
    __syncthreads();
    // GRU1 step 0 (h=0 -> recurrent term is just bias)
    if (tid < 128) {
        int u = tid & 31, bo = 2 * (tid >> 5) * 2;   // bo = 2*bp, bp = tid>>5
        bo = (tid >> 5) * 2;
        float2 xz = *(const float2*)&xg1f[(u)      * 10 + bo];
        float2 xr = *(const float2*)&xg1f[(32 + u) * 10 + bo];
        float2 xh = *(const float2*)&xg1f[(64 + u) * 10 + bo];
        float bz = b1[96 + u], br = b1[128 + u], bh = b1[160 + u];
        u64 hn = gru_gate(pk2(xz.x, xz.y), pk2(bz, bz),
                          pk2(xr.x, xr.y), pk2(br, br),
                          pk2(xh.x, xh.y), pk2(bh, bh), 0ull);
        float n0, n1; upk2(hn, n0, n1);
        *(ulonglong2*)&h1d[u * 8 + bo] = make_ulonglong2(pk2(n0, n0), pk2(n1, n1));
    }
    __syncthreads();

    // gather indices (768 loads over NT threads)
    const int gb0 = tid / 96,          gj0 = tid % 96;
    const int gb1 = (tid + 352) / 96,  gj1 = (tid + 352) % 96;
    const int gb2 = (tid + 704) / 96,  gj2 = (tid + 704) % 96;
    float gv0 = 0.0f, gv1 = 0.0f, gv2 = 0.0f;

    #pragma unroll 1
    for (int k = 0; k < TT; k++) {
        // ================= Phase A: gathers + 3 GEMMs =================
        if (k < TT - 2) {
            int slot = (k + 2) & 31;
            gv0 = __ldg(&g_proj1[tok[gb0 * 32 + slot] * 96 + gj0]);
            gv1 = __ldg(&g_proj1[tok[gb1 * 32 + slot] * 96 + gj1]);
            if (tid < 64)
                gv2 = __ldg(&g_proj1[tok[gb2 * 32 + slot] * 96 + gj2]);
        }
        if (tid < 192) {
            // G3: hm2 = h2 @ kh2 + b2[1]  (2 cols x 4 batches)
            u64 a0 = bq, a1 = bq, a2 = bq, a3 = bq;
            const char* hb = (const char*)h2d + hf3 * 32;
            #pragma unroll
            for (int u = 0; u < 64; u++) {
                ulonglong2 hA = *(const ulonglong2*)(hb + u * 64);
                ulonglong2 hB = *(const ulonglong2*)(hb + u * 64 + 16);
                a0 = ffma2(wq[u], hA.x, a0); a1 = ffma2(wq[u], hA.y, a1);
                a2 = ffma2(wq[u], hB.x, a2); a3 = ffma2(wq[u], hB.y, a3);
            }
            float* o0 = hm2f + (2 * c3) * 10 + 4 * hf3;
            float f0, f1;
            upk2(a0, f0, f1); o0[0] = f0; o0[10] = f1;
            upk2(a1, f0, f1); o0[1] = f0; o0[11] = f1;
            upk2(a2, f0, f1); o0[2] = f0; o0[12] = f1;
            upk2(a3, f0, f1); o0[3] = f0; o0[13] = f1;
        } else if (tid < 288) {
            // G2: xg2 = h1 @ kx2 + b2[0]  (2 cols x 8 batches)
            u64 a[8];
            #pragma unroll
            for (int p = 0; p < 8; p++) a[p] = bq;
            #pragma unroll
            for (int u = 0; u < 32; u++) {
                const ulonglong2* hp = (const ulonglong2*)&h1d[u * 8];
                ulonglong2 hA = hp[0], hB = hp[1], hC = hp[2], hD = hp[3];
                a[0] = ffma2(wq[u], hA.x, a[0]); a[1] = ffma2(wq[u], hA.y, a[1]);
                a[2] = ffma2(wq[u], hB.x, a[2]); a[3] = ffma2(wq[u], hB.y, a[3]);
                a[4] = ffma2(wq[u], hC.x, a[4]); a[5] = ffma2(wq[u], hC.y, a[5]);
                a[6] = ffma2(wq[u], hD.x, a[6]); a[7] = ffma2(wq[u], hD.y, a[7]);
            }
            float* o0 = xg2f + (2 * c2) * 10;
            #pragma unroll
            for (int p = 0; p < 8; p++) {
                float f0, f1; upk2(a[p], f0, f1);
                o0[p] = f0; o0[10 + p] = f1;
            }
        } else if (tid < 336) {
            // G1: hm1(t+1) = h1 @ kh1 + b1[1]  (2 cols x 8 batches)
            u64 a[8];
            #pragma unroll
            for (int p = 0; p < 8; p++) a[p] = bq;
            #pragma unroll
            for (int u = 0; u < 32; u++) {
                const ulonglong2* hp = (const ulonglong2*)&h1d[u * 8];
                ulonglong2 hA = hp[0], hB = hp[1], hC = hp[2], hD = hp[3];
                a[0] = ffma2(wq[u], hA.x, a[0]); a[1] = ffma2(wq[u], hA.y, a[1]);
                a[2] = ffma2(wq[u], hB.x, a[2]); a[3] = ffma2(wq[u], hB.y, a[3]);
                a[4] = ffma2(wq[u], hC.x, a[4]); a[5] = ffma2(wq[u], hC.y, a[5]);
                a[6] = ffma2(wq[u], hD.x, a[6]); a[7] = ffma2(wq[u], hD.y, a[7]);
            }
            float* o0 = hm1f + (2 * c1) * 10;
            #pragma unroll
            for (int p = 0; p < 8; p++) {
                float f0, f1; upk2(a[p], f0, f1);
                o0[p] = f0; o0[10 + p] = f1;
            }
        }
        __syncthreads();

        // ================= Phase B: gates + gather stores =================
        if (k < TT - 2) {
            int buf = (k + 2) & 1;
            float* xb = xg1f + buf * 960;
            xb[gj0 * 10 + gb0] = gv0;
            xb[gj1 * 10 + gb1] = gv1;
            if (tid < 64) xb[gj2 * 10 + gb2] = gv2;
        }
        if (tid < 128) {
            // GRU2 gates, step k (2 batch pairs per thread)
            int u = tid & 63, gh = tid >> 6;
            #pragma unroll
            for (int pp = 0; pp < 2; pp++) {
                int bo = 2 * (2 * gh + pp);
                float2 xz = *(const float2*)&xg2f[(u)       * 10 + bo];
                float2 xr = *(const float2*)&xg2f[(64 + u)  * 10 + bo];
                float2 xh = *(const float2*)&xg2f[(128 + u) * 10 + bo];
                float2 hz = *(const float2*)&hm2f[(u)       * 10 + bo];
                float2 hr = *(const float2*)&hm2f[(64 + u)  * 10 + bo];
                float2 hh = *(const float2*)&hm2f[(128 + u) * 10 + bo];
                float4 hv = *(const float4*)&h2d[u * 8 + bo];
                u64 hn = gru_gate(pk2(xz.x, xz.y), pk2(hz.x, hz.y),
                                  pk2(xr.x, xr.y), pk2(hr.x, hr.y),
                                  pk2(xh.x, xh.y), pk2(hh.x, hh.y),
                                  pk2(hv.x, hv.z));
                float n0, n1; upk2(hn, n0, n1);
                *(ulonglong2*)&h2d[u * 8 + bo] =
                    make_ulonglong2(pk2(n0, n0), pk2(n1, n1));
            }
        } else if (tid < 256 && k < TT - 1) {
            // GRU1 gates, step k+1
            int t2 = tid - 128;
            int u = t2 & 31, bo = 2 * (t2 >> 5);
            const float* xb = xg1f + ((k + 1) & 1) * 960;
            float2 xz = *(const float2*)&xb[(u)      * 10 + bo];
            float2 xr = *(const float2*)&xb[(32 + u) * 10 + bo];
            float2 xh = *(const float2*)&xb[(64 + u) * 10 + bo];
            float2 hz = *(const float2*)&hm1f[(u)      * 10 + bo];
            float2 hr = *(const float2*)&hm1f[(32 + u) * 10 + bo];
            float2 hh = *(const float2*)&hm1f[(64 + u) * 10 + bo];
            float4 hv = *(const float4*)&h1d[u * 8 + bo];
            u64 hn = gru_gate(pk2(xz.x, xz.y), pk2(hz.x, hz.y),
                              pk2(xr.x, xr.y), pk2(hr.x, hr.y),
                              pk2(xh.x, xh.y), pk2(hh.x, hh.y),
                              pk2(hv.x, hv.z));
            float n0, n1; upk2(hn, n0, n1);
            *(ulonglong2*)&h1d[u * 8 + bo] =
                make_ulonglong2(pk2(n0, n0), pk2(n1, n1));
        }
        if (((k + 3) & 31) == 0 && (k + 3) < TT && tid < 256) {
            int b = tid >> 5, o = tid & 31;
            tok[b * 32 + o] = tokens[(b0 + b) * TT + (k + 3) + o];
        }
        __syncthreads();
    }

    // ================= Epilogue: GLU + dense + sigmoid =================
    float* ags = (float*)(sbuf + OFF_AGS);   // [8][256]
    float* gws = (float*)(sbuf + OFF_GWS);   // [8][128]
    if (tid < 256) {
        int c = tid;
        float bgv = bg[c];
        u64 acc0 = pk2(bgv, bgv), acc1 = acc0, acc2 = acc0, acc3 = acc0;
        #pragma unroll
        for (int u = 0; u < 64; u++) {
            const float4* hp = (const float4*)&h2d[u * 8];
            float4 v01 = hp[0], v23 = hp[1], v45 = hp[2], v67 = hp[3];
            float wv = __ldg(&wg[u * 256 + c]);
            u64 w = pk2(wv, wv);
            acc0 = ffma2(w, pk2(v01.x, v01.z), acc0);
            acc1 = ffma2(w, pk2(v23.x, v23.z), acc1);
            acc2 = ffma2(w, pk2(v45.x, v45.z), acc2);
            acc3 = ffma2(w, pk2(v67.x, v67.z), acc3);
        }
        float f0, f1;
        upk2(acc0, f0, f1); ags[0 * 256 + c] = f0; ags[1 * 256 + c] = f1;
        upk2(acc1, f0, f1); ags[2 * 256 + c] = f0; ags[3 * 256 + c] = f1;
        upk2(acc2, f0, f1); ags[4 * 256 + c] = f0; ags[5 * 256 + c] = f1;
        upk2(acc3, f0, f1); ags[6 * 256 + c] = f0; ags[7 * 256 + c] = f1;
    }
    __syncthreads();
    for (int i = tid; i < 1024; i += NT) {
        int b = i >> 7, kk = i & 127;
        float g = ags[b * 256 + kk] * sgm(ags[b * 256 + 128 + kk]);
        gws[b * 128 + kk] = g * __ldg(&wd[kk]);
    }
    __syncthreads();
    if (tid < BB) {
        float s = bd[0];
        #pragma unroll
        for (int kk = 0; kk < 128; kk++) s += gws[tid * 128 + kk];
        out[b0 + tid] = sgm(s);
    }
}

// ---------------------------------------------------------------------------
extern "C" void kernel_launch(void* const* d_in, const int* in_sizes, int n_in,
                              void* d_out, int out_size) {
    (void)in_sizes; (void)n_in; (void)out_size;
    const int*   tokens = (const int*)  d_in[0];
    const float* emb    = (const float*)d_in[1];
    const float* kx1    = (const float*)d_in[2];
    const float* kh1    = (const float*)d_in[3];
    const float* b1     = (const float*)d_in[4];
    const float* kx2    = (const float*)d_in[5];
    const float* kh2    = (const float*)d_in[6];
    const float* b2     = (const float*)d_in[7];
    const float* wg     = (const float*)d_in[8];
    const float* bg     = (const float*)d_in[9];
    const float* wd     = (const float*)d_in[10];
    const float* bd     = (const float*)d_in[11];

    proj_kernel<<<(VSZ + 15) / 16, 256>>>(emb, kx1, b1);
    rnn_kernel<<<BSZ / BB, NT>>>(tokens, kh1, b1, kx2, kh2, b2,
                                 wg, bg, wd, bd, (float*)d_out);
}